// round 3
// baseline (speedup 1.0000x reference)
#include <cuda_runtime.h>
#include <cstdint>

// Problem constants
#define B_   8
#define CIN  67
#define C2   128
#define CO   64
#define NN   16384
#define TN   128
#define NT   (NN / TN)
#define CH   8              // chunks per K1 CTA -> 16x8 = 128 CTAs (one wave)
#define EPSV 1e-5f

// -------- scratch (static device memory; no allocations) --------
__device__ float g_WqT[68 * C2];   // transposed: [i][c], lane-coalesced
__device__ float g_WkT[68 * C2];
__device__ float g_WvT[68 * C2];
__device__ float g_bq[C2];
__device__ float g_bk[C2];
__device__ float g_bv[C2];
__device__ float g_bf[CO];
__device__ float g_kv[B_ * C2 * C2];   // per-batch 128x128 k.v^T
__device__ float g_M[B_ * CO * C2];    // per-batch (scale_f*Wf).kv^T  [b][o][c]

typedef unsigned long long u64;

// -------- packed f32x2 helpers (B300 FFMA2 path) --------
__device__ __forceinline__ u64 pk2(float x, float y) {
    u64 r;
    asm("mov.b64 %0, {%1, %2};" : "=l"(r) : "f"(x), "f"(y));
    return r;
}
__device__ __forceinline__ u64 fma2(u64 a, u64 b, u64 c) {
    u64 d;
    asm("fma.rn.f32x2 %0, %1, %2, %3;" : "=l"(d) : "l"(a), "l"(b), "l"(c));
    return d;
}
__device__ __forceinline__ float2 uf2(u64 u) {
    float2 r;
    r.x = __uint_as_float((unsigned)(u & 0xffffffffull));
    r.y = __uint_as_float((unsigned)(u >> 32));
    return r;
}

// -------- cp.async helpers --------
__device__ __forceinline__ void cpasync16(uint32_t dst, const void* src) {
    asm volatile("cp.async.cg.shared.global [%0], [%1], 16;" :: "r"(dst), "l"(src));
}
__device__ __forceinline__ void cp_commit() {
    asm volatile("cp.async.commit_group;");
}
__device__ __forceinline__ void cp_wait0() {
    asm volatile("cp.async.wait_group 0;");
}
__device__ __forceinline__ uint32_t s2u(const void* p) {
    uint32_t a;
    asm("{ .reg .u64 t; cvta.to.shared.u64 t, %1; cvt.u32.u64 %0, t; }" : "=r"(a) : "l"(p));
    return a;
}

// ================= K0: fold BN into (transposed) weights, zero kv ============
__global__ void k0_prep(const float* __restrict__ Wq, const float* __restrict__ Wk,
                        const float* __restrict__ Wv,
                        const float* __restrict__ bnq, const float* __restrict__ bnk,
                        const float* __restrict__ bnv, const float* __restrict__ bnf) {
    int idx = blockIdx.x * blockDim.x + threadIdx.x;
    const int FW = C2 * CIN;  // 8576
    if (idx < 3 * FW) {
        int p = idx / FW, r = idx % FW, ch = r / CIN, i = r % CIN;
        const float* W  = (p == 0) ? Wq  : (p == 1) ? Wk  : Wv;
        const float* bn = (p == 0) ? bnq : (p == 1) ? bnk : bnv;
        float sc = bn[ch] * rsqrtf(bn[3 * C2 + ch] + EPSV);
        float* D = (p == 0) ? g_WqT : (p == 1) ? g_WkT : g_WvT;
        D[i * C2 + ch] = sc * W[ch * CIN + i];   // transposed store
        return;
    }
    idx -= 3 * FW;
    if (idx < 3 * C2) {
        int p = idx / C2, ch = idx % C2;
        const float* bn = (p == 0) ? bnq : (p == 1) ? bnk : bnv;
        float sc = bn[ch] * rsqrtf(bn[3 * C2 + ch] + EPSV);
        float sh = bn[C2 + ch] - bn[2 * C2 + ch] * sc;
        float* D = (p == 0) ? g_bq : (p == 1) ? g_bk : g_bv;
        D[ch] = sh;
        return;
    }
    idx -= 3 * C2;
    if (idx < CO) {
        float sc = bnf[idx] * rsqrtf(bnf[3 * CO + idx] + EPSV);
        g_bf[idx] = bnf[CO + idx] - bnf[2 * CO + idx] * sc;
        return;
    }
    idx -= CO;
    if (idx < B_ * C2 * C2) g_kv[idx] = 0.0f;
}

// ================= K1: k/v projection + kv accumulation (chunked, dbl-buf) ===
// smem: xs[2][CIN*TN] double-buffered via cp.async, kT/vT transposed [TN][132]
// grid: (NT/CH, B_) = (16, 8); each CTA processes CH tiles, commits kv once.
__global__ void __launch_bounds__(512, 1)
k1_kv_accum(const float* __restrict__ x) {
    extern __shared__ float sm[];
    float* xs0 = sm;                           // 8576
    float* xs1 = sm + CIN * TN;                // 8576
    float* kT  = sm + 2 * CIN * TN;            // 128*132 = 16896
    float* vT  = kT + TN * 132;                // 16896
    const int tid = threadIdx.x;
    const int b = blockIdx.y;
    const float* xbb = x + (size_t)b * CIN * NN;

    // persistent kv partials: 4 c-rows x 8 d-cols per thread (as 16 f32x2)
    const int ci = tid & 31, di = tid >> 5;    // 32 x 16 thread grid
    const int c0 = ci * 4, d0 = di * 8;
    u64 acc[16];
#pragma unroll
    for (int m = 0; m < 16; m++) acc[m] = 0ull;

    const int cc = tid & (C2 - 1);             // phase-1 channel (lane-consecutive)
    const int gg = tid >> 7;                   // phase-1 n-group (0..3)

    const int NF4 = (CIN * TN) / 4;            // 2144 float4s per tile

    // prefetch chunk 0 into xs0
    {
        const float* xb = xbb + (size_t)(blockIdx.x * CH) * TN;
        uint32_t d = s2u(xs0);
        for (int f = tid; f < NF4; f += 512) {
            int row = f >> 5, col4 = f & 31;
            cpasync16(d + (uint32_t)(row * TN + col4 * 4) * 4,
                      xb + (size_t)row * NN + col4 * 4);
        }
        cp_commit();
    }

    int cur = 0;
    for (int chx = 0; chx < CH; chx++) {
        cp_wait0();
        __syncthreads();   // xs[cur] ready; prior phase2 done with kT/vT; prev phase1 done with xs[1-cur]
        float* xs = cur ? xs1 : xs0;

        // prefetch next chunk into the other buffer (overlaps with compute)
        if (chx + 1 < CH) {
            const float* xb = xbb + (size_t)((blockIdx.x * CH + chx + 1)) * TN;
            uint32_t d = s2u(cur ? xs0 : xs1);
            for (int f = tid; f < NF4; f += 512) {
                int row = f >> 5, col4 = f & 31;
                cpasync16(d + (uint32_t)(row * TN + col4 * 4) * 4,
                          xb + (size_t)row * NN + col4 * 4);
            }
        }
        cp_commit();

        // ---- phase 1: k,v = relu(W'x + b'), stored transposed ----
        {
            const float bk = g_bk[cc], bv = g_bv[cc];
#pragma unroll
            for (int h = 0; h < 2; h++) {
                const int nb = gg * 32 + h * 16;
                u64 ak[8], av[8];
#pragma unroll
                for (int j = 0; j < 8; j++) { ak[j] = 0ull; av[j] = 0ull; }
                for (int i = 0; i < CIN; i++) {
                    float wk = __ldg(g_WkT + i * C2 + cc);   // coalesced
                    float wv = __ldg(g_WvT + i * C2 + cc);
                    u64 wk2 = pk2(wk, wk), wv2 = pk2(wv, wv);
                    const float4* xp = (const float4*)(xs + i * TN + nb);
#pragma unroll
                    for (int j = 0; j < 4; j++) {
                        float4 t = xp[j];
                        u64 x01 = pk2(t.x, t.y), x23 = pk2(t.z, t.w);
                        ak[2 * j]     = fma2(x01, wk2, ak[2 * j]);
                        ak[2 * j + 1] = fma2(x23, wk2, ak[2 * j + 1]);
                        av[2 * j]     = fma2(x01, wv2, av[2 * j]);
                        av[2 * j + 1] = fma2(x23, wv2, av[2 * j + 1]);
                    }
                }
#pragma unroll
                for (int j = 0; j < 8; j++) {
                    float2 a = uf2(ak[j]);
                    float2 w = uf2(av[j]);
                    int n = nb + 2 * j;
                    kT[n * 132 + cc]       = fmaxf(a.x + bk, 0.0f);
                    kT[(n + 1) * 132 + cc] = fmaxf(a.y + bk, 0.0f);
                    vT[n * 132 + cc]       = fmaxf(w.x + bv, 0.0f);
                    vT[(n + 1) * 132 + cc] = fmaxf(w.y + bv, 0.0f);
                }
            }
        }
        __syncthreads();

        // ---- phase 2: acc[c][d] += sum_n k[c][n]*v[d][n] ----
        for (int n = 0; n < TN; n++) {
            float4 kk = *(const float4*)(kT + n * 132 + c0);      // 16B lane stride: conflict-free
            const float4* vp = (const float4*)(vT + n * 132 + d0); // broadcast within warp
            float4 va = vp[0], vb = vp[1];
            u64 v0 = pk2(va.x, va.y), v1 = pk2(va.z, va.w);
            u64 v2 = pk2(vb.x, vb.y), v3 = pk2(vb.z, vb.w);
            u64 kd0 = pk2(kk.x, kk.x), kd1 = pk2(kk.y, kk.y);
            u64 kd2 = pk2(kk.z, kk.z), kd3 = pk2(kk.w, kk.w);
            acc[0]  = fma2(kd0, v0, acc[0]);
            acc[1]  = fma2(kd0, v1, acc[1]);
            acc[2]  = fma2(kd0, v2, acc[2]);
            acc[3]  = fma2(kd0, v3, acc[3]);
            acc[4]  = fma2(kd1, v0, acc[4]);
            acc[5]  = fma2(kd1, v1, acc[5]);
            acc[6]  = fma2(kd1, v2, acc[6]);
            acc[7]  = fma2(kd1, v3, acc[7]);
            acc[8]  = fma2(kd2, v0, acc[8]);
            acc[9]  = fma2(kd2, v1, acc[9]);
            acc[10] = fma2(kd2, v2, acc[10]);
            acc[11] = fma2(kd2, v3, acc[11]);
            acc[12] = fma2(kd3, v0, acc[12]);
            acc[13] = fma2(kd3, v1, acc[13]);
            acc[14] = fma2(kd3, v2, acc[14]);
            acc[15] = fma2(kd3, v3, acc[15]);
        }
        cur ^= 1;
    }

    // ---- single kv commit per CTA ----
    float* kvb = g_kv + b * C2 * C2;
#pragma unroll
    for (int a = 0; a < 4; a++)
#pragma unroll
        for (int m = 0; m < 4; m++) {
            float2 r = uf2(acc[a * 4 + m]);
            atomicAdd(&kvb[(c0 + a) * C2 + d0 + 2 * m],     r.x);
            atomicAdd(&kvb[(c0 + a) * C2 + d0 + 2 * m + 1], r.y);
        }
}

// ================= K2: M[b][o][c] = scale_f[o] * sum_d Wf[o][d] kv[b][c][d] ==
__global__ void k2_M(const float* __restrict__ Wf, const float* __restrict__ bnf) {
    int idx = blockIdx.x * blockDim.x + threadIdx.x;  // 65536 total
    int b = idx >> 13;
    int r = idx & 8191;
    int o = r >> 7;
    int c = r & 127;
    const float* kvb = g_kv + b * C2 * C2 + c * C2;
    const float* wf = Wf + o * C2;
    float s = 0.0f;
#pragma unroll 8
    for (int d = 0; d < C2; d++) s = fmaf(wf[d], kvb[d], s);
    float sc = bnf[o] * rsqrtf(bnf[3 * CO + o] + EPSV);
    g_M[idx] = sc * s;
}

// ================= K3: q projection + out = relu(M q + b_f) =================
// smem: xs [CIN][TN], qs [C2][132]  (99.5 KB -> 2 CTAs/SM)
__global__ void __launch_bounds__(512, 2)
k3_out(const float* __restrict__ x, float* __restrict__ out) {
    extern __shared__ float sm[];
    float* xs = sm;                       // 8576
    float* qs = sm + CIN * TN;            // 128*132 = 16896
    const int tid = threadIdx.x;
    const int b = blockIdx.y;
    const int n0 = blockIdx.x * TN;

    const float* xb = x + (size_t)b * CIN * NN + n0;
    for (int idx = tid; idx < CIN * TN; idx += 512) {
        int i = idx / TN, n = idx % TN;
        xs[idx] = xb[(size_t)i * NN + n];
    }
    __syncthreads();

    // ---- phase 1: q = relu(Wq'x + bq), stored c-major padded (two half-passes) ----
    {
        const int cc = tid & (C2 - 1);
        const int gg = tid >> 7;
        const float bq = g_bq[cc];
#pragma unroll
        for (int h = 0; h < 2; h++) {
            const int nb = gg * 32 + h * 16;
            u64 aq[8];
#pragma unroll
            for (int j = 0; j < 8; j++) aq[j] = 0ull;
            for (int i = 0; i < CIN; i++) {
                float wq = __ldg(g_WqT + i * C2 + cc);   // coalesced
                u64 w2 = pk2(wq, wq);
                const float4* xp = (const float4*)(xs + i * TN + nb);
#pragma unroll
                for (int j = 0; j < 4; j++) {
                    float4 t = xp[j];
                    aq[2 * j]     = fma2(pk2(t.x, t.y), w2, aq[2 * j]);
                    aq[2 * j + 1] = fma2(pk2(t.z, t.w), w2, aq[2 * j + 1]);
                }
            }
#pragma unroll
            for (int j = 0; j < 8; j++) {
                float2 a = uf2(aq[j]);
                float2 r;
                r.x = fmaxf(a.x + bq, 0.0f);
                r.y = fmaxf(a.y + bq, 0.0f);
                *(float2*)(qs + cc * 132 + nb + 2 * j) = r;
            }
        }
    }
    __syncthreads();

    // ---- phase 2: out[o][n] = relu(sum_c M[o][c]*q[c][n] + bf[o]) ----
    // lane -> 4 consecutive n (16B stride: conflict-free LDS.128); 4 o per thread.
    {
        const int ni = tid & 31, og = tid >> 5;
        const int nb = ni * 4, o0 = og * 4;
        u64 acc[8];
#pragma unroll
        for (int j = 0; j < 8; j++) acc[j] = 0ull;
        const float* M0 = g_M + ((size_t)b * CO + o0) * C2;
        for (int c = 0; c < C2; c += 4) {
            float4 q0 = *(const float4*)(qs + c * 132 + nb);
            float4 q1 = *(const float4*)(qs + (c + 1) * 132 + nb);
            float4 q2 = *(const float4*)(qs + (c + 2) * 132 + nb);
            float4 q3 = *(const float4*)(qs + (c + 3) * 132 + nb);
            u64 qa0 = pk2(q0.x, q0.y), qb0 = pk2(q0.z, q0.w);
            u64 qa1 = pk2(q1.x, q1.y), qb1 = pk2(q1.z, q1.w);
            u64 qa2 = pk2(q2.x, q2.y), qb2 = pk2(q2.z, q2.w);
            u64 qa3 = pk2(q3.x, q3.y), qb3 = pk2(q3.z, q3.w);
#pragma unroll
            for (int a = 0; a < 4; a++) {
                float4 m = __ldg((const float4*)(M0 + a * C2 + c));  // broadcast
                u64 m0 = pk2(m.x, m.x), m1 = pk2(m.y, m.y);
                u64 m2v = pk2(m.z, m.z), m3 = pk2(m.w, m.w);
                acc[2 * a]     = fma2(qa0, m0, acc[2 * a]);
                acc[2 * a + 1] = fma2(qb0, m0, acc[2 * a + 1]);
                acc[2 * a]     = fma2(qa1, m1, acc[2 * a]);
                acc[2 * a + 1] = fma2(qb1, m1, acc[2 * a + 1]);
                acc[2 * a]     = fma2(qa2, m2v, acc[2 * a]);
                acc[2 * a + 1] = fma2(qb2, m2v, acc[2 * a + 1]);
                acc[2 * a]     = fma2(qa3, m3, acc[2 * a]);
                acc[2 * a + 1] = fma2(qb3, m3, acc[2 * a + 1]);
            }
        }
#pragma unroll
        for (int a = 0; a < 4; a++) {
            float bo = g_bf[o0 + a];
            float2 lo = uf2(acc[2 * a]);
            float2 hi = uf2(acc[2 * a + 1]);
            float4 r;
            r.x = fmaxf(lo.x + bo, 0.0f);
            r.y = fmaxf(lo.y + bo, 0.0f);
            r.z = fmaxf(hi.x + bo, 0.0f);
            r.w = fmaxf(hi.y + bo, 0.0f);
            *(float4*)(out + ((size_t)b * CO + o0 + a) * NN + n0 + nb) = r;  // coalesced
        }
    }
}

// ================= launch =================
extern "C" void kernel_launch(void* const* d_in, const int* in_sizes, int n_in,
                              void* d_out, int out_size) {
    const float* x   = (const float*)d_in[0];
    const float* Wq  = (const float*)d_in[1];
    const float* Wk  = (const float*)d_in[2];
    const float* Wv  = (const float*)d_in[3];
    const float* Wf  = (const float*)d_in[4];
    const float* bnq = (const float*)d_in[5];
    const float* bnk = (const float*)d_in[6];
    const float* bnv = (const float*)d_in[7];
    const float* bnf = (const float*)d_in[8];
    float* out = (float*)d_out;

    const int smem1 = (2 * CIN * TN + 2 * TN * 132) * 4;   // 203776 B (dbl-buf xs)
    const int smem3 = (CIN * TN + C2 * 132) * 4;           // 101888 B (occ 2)
    cudaFuncSetAttribute(k1_kv_accum, cudaFuncAttributeMaxDynamicSharedMemorySize, smem1);
    cudaFuncSetAttribute(k3_out,      cudaFuncAttributeMaxDynamicSharedMemorySize, smem3);

    const int prep_total = 3 * C2 * CIN + 3 * C2 + CO + B_ * C2 * C2;
    k0_prep<<<(prep_total + 255) / 256, 256>>>(Wq, Wk, Wv, bnq, bnk, bnv, bnf);
    k1_kv_accum<<<dim3(NT / CH, B_), 512, smem1>>>(x);
    k2_M<<<(B_ * CO * C2) / 256, 256>>>(Wf, bnf);
    k3_out<<<dim3(NT, B_), 512, smem3>>>(x, out);
}

// round 11
// speedup vs baseline: 2.0933x; 2.0933x over previous
#include <cuda_runtime.h>
#include <cuda_bf16.h>
#include <cstdint>

#define B_   8
#define CIN  67
#define KP   80      // K padded to 5 mma k-steps
#define C2   128
#define CO   64
#define NN   16384
#define TN   128
#define CH   8
#define EPSV 1e-5f

typedef __nv_bfloat16 bf16;

// ---- static scratch (no allocations) ----
__device__ __align__(16) bf16 g_WkH[C2 * KP];
__device__ __align__(16) bf16 g_WkL[C2 * KP];
__device__ __align__(16) bf16 g_WvH[C2 * KP];
__device__ __align__(16) bf16 g_WvL[C2 * KP];
__device__ __align__(16) bf16 g_WqH[C2 * KP];
__device__ __align__(16) bf16 g_WqL[C2 * KP];
__device__ float g_bk[C2];
__device__ float g_bv[C2];
__device__ float g_bq[C2];
__device__ float g_bf[CO];
__device__ float g_kv[B_ * C2 * C2];
__device__ float g_M[B_ * CO * C2];

// ---- smem layout (bytes). strides: x/W = 88 bf16, kS/vS/qS/M = 136 bf16 ----
#define XS_ST 88
#define BG_ST 136
#define A_XH  0
#define A_XL  22528
#define A_WKH 45056
#define A_WKL 67584
#define A_WVH 90112
#define A_WVL 112640
#define A_KS  135168
#define A_VS  169984
#define A_SZ  204800
#define P_XH  0
#define P_XL  22528
#define P_WQH 45056
#define P_WQL 67584
#define P_QH  90112
#define P_QL  124928
#define P_MH  159744
#define P_ML  177152
#define P_SZ  194560

// mma.sync m16n8k16 bf16 -> f32 (baseline sm_80+ PTX; compiles for sm_103)
__device__ __forceinline__ void mma16816(float* d, const uint32_t* a, const uint32_t* b) {
    asm volatile(
        "mma.sync.aligned.m16n8k16.row.col.f32.bf16.bf16.f32 "
        "{%0,%1,%2,%3}, {%4,%5,%6,%7}, {%8,%9}, {%0,%1,%2,%3};"
        : "+f"(d[0]), "+f"(d[1]), "+f"(d[2]), "+f"(d[3])
        : "r"(a[0]), "r"(a[1]), "r"(a[2]), "r"(a[3]), "r"(b[0]), "r"(b[1]));
}

// A fragment from row-major [M][K] bf16 (stride S elems), tile (m0,k0)
#define LDA(a, base, m0, k0, S) do { \
    const bf16* _p = (base); \
    (a)[0] = *(const uint32_t*)(_p + ((m0) + g) * (S) + (k0) + 2 * tig); \
    (a)[1] = *(const uint32_t*)(_p + ((m0) + g + 8) * (S) + (k0) + 2 * tig); \
    (a)[2] = *(const uint32_t*)(_p + ((m0) + g) * (S) + (k0) + 2 * tig + 8); \
    (a)[3] = *(const uint32_t*)(_p + ((m0) + g + 8) * (S) + (k0) + 2 * tig + 8); \
} while (0)

// B fragment from [N][K] bf16 storage (stride S elems), tile (k0,n0)
#define LDB(bb, base, k0, n0, S) do { \
    const bf16* _p = (base); \
    (bb)[0] = *(const uint32_t*)(_p + ((n0) + g) * (S) + (k0) + 2 * tig); \
    (bb)[1] = *(const uint32_t*)(_p + ((n0) + g) * (S) + (k0) + 2 * tig + 8); \
} while (0)

__device__ __forceinline__ void split_bf(float v, bf16& hi, bf16& lo) {
    hi = __float2bfloat16(v);
    lo = __float2bfloat16(v - __bfloat162float(hi));
}

// ================= K0: fold BN into hi/lo weights [c][KP]; biases; zero kv ===
__global__ void k0_prep(const float* __restrict__ Wq, const float* __restrict__ Wk,
                        const float* __restrict__ Wv, const float* __restrict__ bnq,
                        const float* __restrict__ bnk, const float* __restrict__ bnv,
                        const float* __restrict__ bnf) {
    int idx = blockIdx.x * blockDim.x + threadIdx.x;
    const int WSZ = C2 * KP;
    if (idx < 3 * WSZ) {
        int p = idx / WSZ, r = idx % WSZ, c = r / KP, i = r % KP;
        const float* W  = (p == 0) ? Wq  : (p == 1) ? Wk  : Wv;
        const float* bn = (p == 0) ? bnq : (p == 1) ? bnk : bnv;
        float sc = bn[c] * rsqrtf(bn[3 * C2 + c] + EPSV);
        float v = (i < CIN) ? sc * W[c * CIN + i] : 0.0f;
        bf16 hi, lo;
        split_bf(v, hi, lo);
        bf16* DH = (p == 0) ? g_WqH : (p == 1) ? g_WkH : g_WvH;
        bf16* DL = (p == 0) ? g_WqL : (p == 1) ? g_WkL : g_WvL;
        DH[c * KP + i] = hi;
        DL[c * KP + i] = lo;
        return;
    }
    idx -= 3 * WSZ;
    if (idx < 3 * C2) {
        int p = idx / C2, c = idx % C2;
        const float* bn = (p == 0) ? bnq : (p == 1) ? bnk : bnv;
        float sc = bn[c] * rsqrtf(bn[3 * C2 + c] + EPSV);
        ((p == 0) ? g_bq : (p == 1) ? g_bk : g_bv)[c] = bn[C2 + c] - bn[2 * C2 + c] * sc;
        return;
    }
    idx -= 3 * C2;
    if (idx < CO) {
        float sc = bnf[idx] * rsqrtf(bnf[3 * CO + idx] + EPSV);
        g_bf[idx] = bnf[CO + idx] - bnf[2 * CO + idx] * sc;
        return;
    }
    idx -= CO;
    if (idx < B_ * C2 * C2) g_kv[idx] = 0.0f;
}

// ================= Pass A: bf16x3 k/v proj + bf16 kv accum (regs) ============
__global__ void __launch_bounds__(256, 1)
k1_kv(const float* __restrict__ x) {
    extern __shared__ char sm[];
    bf16* XH = (bf16*)(sm + A_XH);
    bf16* XL = (bf16*)(sm + A_XL);
    bf16* KS = (bf16*)(sm + A_KS);
    bf16* VS = (bf16*)(sm + A_VS);
    const int tid = threadIdx.x, w = tid >> 5, lane = tid & 31;
    const int g = lane >> 2, tig = lane & 3;
    const int b = blockIdx.y;

    {   // stage 4 weight tiles into padded smem; zero xs (incl pads)
        const bf16* src[4] = {g_WkH, g_WkL, g_WvH, g_WvL};
        bf16* dst[4] = {(bf16*)(sm + A_WKH), (bf16*)(sm + A_WKL),
                        (bf16*)(sm + A_WVH), (bf16*)(sm + A_WVL)};
#pragma unroll
        for (int a4 = 0; a4 < 4; a4++)
            for (int j = tid; j < C2 * KP / 2; j += 256) {
                int c = j / (KP / 2), kk = j % (KP / 2);
                *(uint32_t*)(dst[a4] + c * XS_ST + 2 * kk) =
                    *(const uint32_t*)(src[a4] + c * KP + 2 * kk);
            }
        for (int j = tid; j < (TN * XS_ST) / 2; j += 256) {
            ((uint32_t*)XH)[j] = 0;
            ((uint32_t*)XL)[j] = 0;
        }
    }
    __syncthreads();

    float akv[16][4];
#pragma unroll
    for (int nt = 0; nt < 16; nt++)
#pragma unroll
        for (int q4 = 0; q4 < 4; q4++) akv[nt][q4] = 0.0f;

    for (int chx = 0; chx < CH; chx++) {
        const int n0 = (blockIdx.x * CH + chx) * TN;
        {   // stage x tile: transpose + hi/lo split -> XH/XL [n][i]
            const int n = tid & 127, h = tid >> 7;
            const float* xb = x + (size_t)b * CIN * NN + n0 + n;
            for (int i = h; i < CIN; i += 2) {
                bf16 hi, lo;
                split_bf(xb[(size_t)i * NN], hi, lo);
                XH[n * XS_ST + i] = hi;
                XL[n * XS_ST + i] = lo;
            }
        }
        __syncthreads();

        // k then v projection: D[c][n] = W.x, bf16x3; warp w -> rows 16w..16w+15
#pragma unroll
        for (int pass = 0; pass < 2; pass++) {
            const bf16* WH = (const bf16*)(sm + (pass ? A_WVH : A_WKH));
            const bf16* WL = (const bf16*)(sm + (pass ? A_WVL : A_WKL));
            bf16* OUT = pass ? VS : KS;
            const float* bias = pass ? g_bv : g_bk;
            float acc[16][4];
#pragma unroll
            for (int nt = 0; nt < 16; nt++)
#pragma unroll
                for (int q4 = 0; q4 < 4; q4++) acc[nt][q4] = 0.0f;
#pragma unroll
            for (int ks = 0; ks < 5; ks++) {
                uint32_t aH[4], aL[4];
                LDA(aH, WH, 16 * w, 16 * ks, XS_ST);
                LDA(aL, WL, 16 * w, 16 * ks, XS_ST);
#pragma unroll
                for (int nt = 0; nt < 16; nt++) {
                    uint32_t bH[2], bL[2];
                    LDB(bH, XH, 16 * ks, 8 * nt, XS_ST);
                    LDB(bL, XL, 16 * ks, 8 * nt, XS_ST);
                    mma16816(acc[nt], aH, bH);
                    mma16816(acc[nt], aH, bL);
                    mma16816(acc[nt], aL, bH);
                }
            }
            const float b0v = bias[16 * w + g], b1v = bias[16 * w + g + 8];
#pragma unroll
            for (int nt = 0; nt < 16; nt++) {
                float f0 = fmaxf(acc[nt][0] + b0v, 0.0f);
                float f1 = fmaxf(acc[nt][1] + b0v, 0.0f);
                float f2 = fmaxf(acc[nt][2] + b1v, 0.0f);
                float f3 = fmaxf(acc[nt][3] + b1v, 0.0f);
                __nv_bfloat162 p01 = __floats2bfloat162_rn(f0, f1);
                __nv_bfloat162 p23 = __floats2bfloat162_rn(f2, f3);
                *(uint32_t*)(OUT + (16 * w + g) * BG_ST + 8 * nt + 2 * tig) = *(uint32_t*)&p01;
                *(uint32_t*)(OUT + (16 * w + g + 8) * BG_ST + 8 * nt + 2 * tig) = *(uint32_t*)&p23;
            }
        }
        __syncthreads();

        // kv[c][d] += sum_n k[c][n] v[d][n]; A = kS [c][n], B = vS ([d][n] = [N][K])
#pragma unroll
        for (int ks = 0; ks < 8; ks++) {
            uint32_t aK[4];
            LDA(aK, KS, 16 * w, 16 * ks, BG_ST);
#pragma unroll
            for (int nt = 0; nt < 16; nt++) {
                uint32_t bV[2];
                LDB(bV, VS, 16 * ks, 8 * nt, BG_ST);
                mma16816(akv[nt], aK, bV);
            }
        }
        __syncthreads();   // kS/vS reads done before next chunk overwrites
    }

    // commit kv partials
    float* kvb = g_kv + (size_t)b * C2 * C2;
#pragma unroll
    for (int nt = 0; nt < 16; nt++) {
        atomicAdd(&kvb[(16 * w + g) * C2 + 8 * nt + 2 * tig],     akv[nt][0]);
        atomicAdd(&kvb[(16 * w + g) * C2 + 8 * nt + 2 * tig + 1], akv[nt][1]);
        atomicAdd(&kvb[(16 * w + g + 8) * C2 + 8 * nt + 2 * tig],     akv[nt][2]);
        atomicAdd(&kvb[(16 * w + g + 8) * C2 + 8 * nt + 2 * tig + 1], akv[nt][3]);
    }
}

// ================= K2: M[b][o][c] = scale_f[o] * sum_d Wf[o][d] kv[b][c][d] ==
__global__ void k2_M(const float* __restrict__ Wf, const float* __restrict__ bnf) {
    int idx = blockIdx.x * blockDim.x + threadIdx.x;  // 65536
    int b = idx >> 13, r = idx & 8191, o = r >> 7, c = r & 127;
    const float* kvb = g_kv + (size_t)b * C2 * C2 + (size_t)c * C2;
    const float* wf = Wf + o * C2;
    float s = 0.0f;
#pragma unroll 8
    for (int d = 0; d < C2; d++) s = fmaf(wf[d], kvb[d], s);
    float sc = bnf[o] * rsqrtf(bnf[3 * CO + o] + EPSV);
    g_M[idx] = sc * s;
}

// ================= Pass B: bf16x3 q proj -> bf16x3 out GEMM -> STG ===========
__global__ void __launch_bounds__(256, 1)
k3_out(const float* __restrict__ x, float* __restrict__ out) {
    extern __shared__ char sm[];
    bf16* XH = (bf16*)(sm + P_XH);
    bf16* XL = (bf16*)(sm + P_XL);
    bf16* QH = (bf16*)(sm + P_QH);
    bf16* QL = (bf16*)(sm + P_QL);
    bf16* MH = (bf16*)(sm + P_MH);
    bf16* ML = (bf16*)(sm + P_ML);
    const int tid = threadIdx.x, w = tid >> 5, lane = tid & 31;
    const int g = lane >> 2, tig = lane & 3;
    const int b = blockIdx.y;

    {   // stage Wq hi/lo, M hi/lo; zero xs
        const bf16* src[2] = {g_WqH, g_WqL};
        bf16* dst[2] = {(bf16*)(sm + P_WQH), (bf16*)(sm + P_WQL)};
#pragma unroll
        for (int a2 = 0; a2 < 2; a2++)
            for (int j = tid; j < C2 * KP / 2; j += 256) {
                int c = j / (KP / 2), kk = j % (KP / 2);
                *(uint32_t*)(dst[a2] + c * XS_ST + 2 * kk) =
                    *(const uint32_t*)(src[a2] + c * KP + 2 * kk);
            }
        const float* Mb = g_M + ((size_t)b << 13);
        for (int j = tid; j < CO * C2; j += 256) {
            int o = j >> 7, c = j & 127;
            bf16 hi, lo;
            split_bf(Mb[j], hi, lo);
            MH[o * BG_ST + c] = hi;
            ML[o * BG_ST + c] = lo;
        }
        for (int j = tid; j < (TN * XS_ST) / 2; j += 256) {
            ((uint32_t*)XH)[j] = 0;
            ((uint32_t*)XL)[j] = 0;
        }
    }
    __syncthreads();

    const bf16* WQH = (const bf16*)(sm + P_WQH);
    const bf16* WQL = (const bf16*)(sm + P_WQL);
    const int o0 = 16 * (w & 3), nbh = 64 * (w >> 2);

    for (int chx = 0; chx < CH; chx++) {
        const int n0 = (blockIdx.x * CH + chx) * TN;
        {   // stage x tile
            const int n = tid & 127, h = tid >> 7;
            const float* xb = x + (size_t)b * CIN * NN + n0 + n;
            for (int i = h; i < CIN; i += 2) {
                bf16 hi, lo;
                split_bf(xb[(size_t)i * NN], hi, lo);
                XH[n * XS_ST + i] = hi;
                XL[n * XS_ST + i] = lo;
            }
        }
        __syncthreads();

        // q proj: D[c][n]; epilogue -> qS stored [n][c] hi/lo (for out-mma B reads)
        {
            float acc[16][4];
#pragma unroll
            for (int nt = 0; nt < 16; nt++)
#pragma unroll
                for (int q4 = 0; q4 < 4; q4++) acc[nt][q4] = 0.0f;
#pragma unroll
            for (int ks = 0; ks < 5; ks++) {
                uint32_t aH[4], aL[4];
                LDA(aH, WQH, 16 * w, 16 * ks, XS_ST);
                LDA(aL, WQL, 16 * w, 16 * ks, XS_ST);
#pragma unroll
                for (int nt = 0; nt < 16; nt++) {
                    uint32_t bH[2], bL[2];
                    LDB(bH, XH, 16 * ks, 8 * nt, XS_ST);
                    LDB(bL, XL, 16 * ks, 8 * nt, XS_ST);
                    mma16816(acc[nt], aH, bH);
                    mma16816(acc[nt], aH, bL);
                    mma16816(acc[nt], aL, bH);
                }
            }
            const float b0v = g_bq[16 * w + g], b1v = g_bq[16 * w + g + 8];
#pragma unroll
            for (int nt = 0; nt < 16; nt++) {
                float f0 = fmaxf(acc[nt][0] + b0v, 0.0f);
                float f1 = fmaxf(acc[nt][1] + b0v, 0.0f);
                float f2 = fmaxf(acc[nt][2] + b1v, 0.0f);
                float f3 = fmaxf(acc[nt][3] + b1v, 0.0f);
                int na = 8 * nt + 2 * tig, nb2 = na + 1;
                bf16 h0, l0, h1, l1, h2, l2, h3, l3;
                split_bf(f0, h0, l0);
                split_bf(f1, h1, l1);
                split_bf(f2, h2, l2);
                split_bf(f3, h3, l3);
                QH[na * BG_ST + 16 * w + g] = h0;  QL[na * BG_ST + 16 * w + g] = l0;
                QH[nb2 * BG_ST + 16 * w + g] = h1; QL[nb2 * BG_ST + 16 * w + g] = l1;
                QH[na * BG_ST + 16 * w + g + 8] = h2;  QL[na * BG_ST + 16 * w + g + 8] = l2;
                QH[nb2 * BG_ST + 16 * w + g + 8] = h3; QL[nb2 * BG_ST + 16 * w + g + 8] = l3;
            }
        }
        __syncthreads();

        // out[o][n] = sum_c M[o][c] q[c][n]; warp: o-tile (w&3), n-half (w>>2)
        {
            float acc[8][4];
#pragma unroll
            for (int nt = 0; nt < 8; nt++)
#pragma unroll
                for (int q4 = 0; q4 < 4; q4++) acc[nt][q4] = 0.0f;
#pragma unroll
            for (int ks = 0; ks < 8; ks++) {
                uint32_t aH[4], aL[4];
                LDA(aH, MH, o0, 16 * ks, BG_ST);
                LDA(aL, ML, o0, 16 * ks, BG_ST);
#pragma unroll
                for (int nt = 0; nt < 8; nt++) {
                    uint32_t bH[2], bL[2];
                    LDB(bH, QH, 16 * ks, nbh + 8 * nt, BG_ST);
                    LDB(bL, QL, 16 * ks, nbh + 8 * nt, BG_ST);
                    mma16816(acc[nt], aH, bH);
                    mma16816(acc[nt], aH, bL);
                    mma16816(acc[nt], aL, bH);
                }
            }
            const float bo0 = g_bf[o0 + g], bo1 = g_bf[o0 + g + 8];
            float* ob0 = out + ((size_t)(b * CO + o0 + g)) * NN + n0 + nbh;
            float* ob1 = out + ((size_t)(b * CO + o0 + g + 8)) * NN + n0 + nbh;
#pragma unroll
            for (int nt = 0; nt < 8; nt++) {
                float2 v0, v1;
                v0.x = fmaxf(acc[nt][0] + bo0, 0.0f);
                v0.y = fmaxf(acc[nt][1] + bo0, 0.0f);
                v1.x = fmaxf(acc[nt][2] + bo1, 0.0f);
                v1.y = fmaxf(acc[nt][3] + bo1, 0.0f);
                *(float2*)(ob0 + 8 * nt + 2 * tig) = v0;
                *(float2*)(ob1 + 8 * nt + 2 * tig) = v1;
            }
        }
        __syncthreads();   // qS reads done before next chunk overwrites
    }
}

// ================= launch =================
extern "C" void kernel_launch(void* const* d_in, const int* in_sizes, int n_in,
                              void* d_out, int out_size) {
    const float* x   = (const float*)d_in[0];
    const float* Wq  = (const float*)d_in[1];
    const float* Wk  = (const float*)d_in[2];
    const float* Wv  = (const float*)d_in[3];
    const float* Wf  = (const float*)d_in[4];
    const float* bnq = (const float*)d_in[5];
    const float* bnk = (const float*)d_in[6];
    const float* bnv = (const float*)d_in[7];
    const float* bnf = (const float*)d_in[8];
    float* out = (float*)d_out;

    cudaFuncSetAttribute(k1_kv,  cudaFuncAttributeMaxDynamicSharedMemorySize, A_SZ);
    cudaFuncSetAttribute(k3_out, cudaFuncAttributeMaxDynamicSharedMemorySize, P_SZ);

    const int prep = 3 * C2 * KP + 3 * C2 + CO + B_ * C2 * C2;
    k0_prep<<<(prep + 255) / 256, 256>>>(Wq, Wk, Wv, bnq, bnk, bnv, bnf);
    k1_kv<<<dim3(16, B_), 256, A_SZ>>>(x);
    k2_M<<<(B_ * CO * C2) / 256, 256>>>(Wf, bnf);
    k3_out<<<dim3(16, B_), 256, P_SZ>>>(x, out);
}

// round 14
// speedup vs baseline: 2.3746x; 1.1344x over previous
#include <cuda_runtime.h>
#include <cuda_bf16.h>
#include <cstdint>

#define B_   8
#define CIN  67
#define KP   80
#define C2   128
#define CO   64
#define NN   16384
#define TN   128
#define CH   8
#define EPSV 1e-5f

typedef __nv_bfloat16 bf16;

// ---- static scratch ----
__device__ __align__(16) bf16 g_WkH[C2 * KP];
__device__ __align__(16) bf16 g_WkL[C2 * KP];
__device__ __align__(16) bf16 g_WvH[C2 * KP];
__device__ __align__(16) bf16 g_WvL[C2 * KP];
__device__ __align__(16) bf16 g_WqH[C2 * KP];
__device__ __align__(16) bf16 g_WqL[C2 * KP];
__device__ float g_bk[C2];
__device__ float g_bv[C2];
__device__ float g_bq[C2];
__device__ float g_bf[CO];
__device__ float g_kv[B_ * C2 * C2];
__device__ float g_M[B_ * CO * C2];

// ---- smem (bytes). x/W stride 88 bf16; KS/VS/Q/M stride 136 bf16 ----
#define XS_ST 88
#define BG_ST 136
#define A_XH  0
#define A_XL  22528
#define A_WVH 45056
#define A_WVL 67584
#define A_KS0 90112         /* KS+VS pair per buffer: 2x34816 */
#define ABUF  69632
#define A_SZ  229376        /* 224KB */
#define P_XH  0
#define P_XL  22528
#define P_MH  45056
#define P_ML  62464
#define P_Q0H 79872
#define PBUF  69632
#define P_SZ  219136        /* 214KB */

__device__ __forceinline__ void mma16816(float* d, const uint32_t* a, const uint32_t* b) {
    asm volatile(
        "mma.sync.aligned.m16n8k16.row.col.f32.bf16.bf16.f32 "
        "{%0,%1,%2,%3}, {%4,%5,%6,%7}, {%8,%9}, {%0,%1,%2,%3};"
        : "+f"(d[0]), "+f"(d[1]), "+f"(d[2]), "+f"(d[3])
        : "r"(a[0]), "r"(a[1]), "r"(a[2]), "r"(a[3]), "r"(b[0]), "r"(b[1]));
}
#define LDA(a, base, m0, k0, S) do { \
    const bf16* _p = (base); \
    (a)[0] = *(const uint32_t*)(_p + ((m0) + g) * (S) + (k0) + 2 * tig); \
    (a)[1] = *(const uint32_t*)(_p + ((m0) + g + 8) * (S) + (k0) + 2 * tig); \
    (a)[2] = *(const uint32_t*)(_p + ((m0) + g) * (S) + (k0) + 2 * tig + 8); \
    (a)[3] = *(const uint32_t*)(_p + ((m0) + g + 8) * (S) + (k0) + 2 * tig + 8); \
} while (0)
#define LDB(bb, base, k0, n0, S) do { \
    const bf16* _p = (base); \
    (bb)[0] = *(const uint32_t*)(_p + ((n0) + g) * (S) + (k0) + 2 * tig); \
    (bb)[1] = *(const uint32_t*)(_p + ((n0) + g) * (S) + (k0) + 2 * tig + 8); \
} while (0)
#define BARSYNC(id, cnt) asm volatile("bar.sync %0, %1;" :: "r"(id), "r"(cnt) : "memory")
#define BARARR(id, cnt)  asm volatile("bar.arrive %0, %1;" :: "r"(id), "r"(cnt) : "memory")

__device__ __forceinline__ void split_bf(float v, bf16& hi, bf16& lo) {
    hi = __float2bfloat16(v);
    lo = __float2bfloat16(v - __bfloat162float(hi));
}

// ================= K0 =================
__global__ void k0_prep(const float* __restrict__ Wq, const float* __restrict__ Wk,
                        const float* __restrict__ Wv, const float* __restrict__ bnq,
                        const float* __restrict__ bnk, const float* __restrict__ bnv,
                        const float* __restrict__ bnf) {
    int idx = blockIdx.x * blockDim.x + threadIdx.x;
    const int WSZ = C2 * KP;
    if (idx < 3 * WSZ) {
        int p = idx / WSZ, r = idx % WSZ, c = r / KP, i = r % KP;
        const float* W  = (p == 0) ? Wq  : (p == 1) ? Wk  : Wv;
        const float* bn = (p == 0) ? bnq : (p == 1) ? bnk : bnv;
        float sc = bn[c] * rsqrtf(bn[3 * C2 + c] + EPSV);
        float v = (i < CIN) ? sc * W[c * CIN + i] : 0.0f;
        bf16 hi, lo;
        split_bf(v, hi, lo);
        bf16* DH = (p == 0) ? g_WqH : (p == 1) ? g_WkH : g_WvH;
        bf16* DL = (p == 0) ? g_WqL : (p == 1) ? g_WkL : g_WvL;
        DH[c * KP + i] = hi;
        DL[c * KP + i] = lo;
        return;
    }
    idx -= 3 * WSZ;
    if (idx < 3 * C2) {
        int p = idx / C2, c = idx % C2;
        const float* bn = (p == 0) ? bnq : (p == 1) ? bnk : bnv;
        float sc = bn[c] * rsqrtf(bn[3 * C2 + c] + EPSV);
        ((p == 0) ? g_bq : (p == 1) ? g_bk : g_bv)[c] = bn[C2 + c] - bn[2 * C2 + c] * sc;
        return;
    }
    idx -= 3 * C2;
    if (idx < CO) {
        float sc = bnf[idx] * rsqrtf(bnf[3 * CO + idx] + EPSV);
        g_bf[idx] = bnf[CO + idx] - bnf[2 * CO + idx] * sc;
        return;
    }
    idx -= CO;
    if (idx < B_ * C2 * C2) g_kv[idx] = 0.0f;
}

// ================= Pass A: warp-specialized k/v proj -> kv accum =============
__global__ void __launch_bounds__(512, 1)
k1_kv(const float* __restrict__ x) {
    extern __shared__ char sm[];
    bf16* XH = (bf16*)(sm + A_XH);
    bf16* XL = (bf16*)(sm + A_XL);
    bf16* WVH = (bf16*)(sm + A_WVH);
    bf16* WVL = (bf16*)(sm + A_WVL);
    const int tid = threadIdx.x, w = tid >> 5, lane = tid & 31;
    const int g = lane >> 2, tig = lane & 3;
    const int b = blockIdx.y;

    for (int j = tid; j < C2 * KP / 2; j += 512) {
        int c = j / (KP / 2), kk = j % (KP / 2);
        *(uint32_t*)(WVH + c * XS_ST + 2 * kk) = *(const uint32_t*)(g_WvH + c * KP + 2 * kk);
        *(uint32_t*)(WVL + c * XS_ST + 2 * kk) = *(const uint32_t*)(g_WvL + c * KP + 2 * kk);
    }
    for (int j = tid; j < (TN * XS_ST) / 2; j += 512) {
        ((uint32_t*)XH)[j] = 0;
        ((uint32_t*)XL)[j] = 0;
    }
    __syncthreads();

    if (w < 8) {
        // ---------------- producer: stage x, k-proj (regs), v-proj (smem) ----
        uint32_t wkH[5][4], wkL[5][4];
#pragma unroll
        for (int ks = 0; ks < 5; ks++) {
            LDA(wkH[ks], g_WkH, 16 * w, 16 * ks, KP);
            LDA(wkL[ks], g_WkL, 16 * w, 16 * ks, KP);
        }
        const float bk0 = g_bk[16 * w + g], bk1 = g_bk[16 * w + g + 8];
        const float bv0 = g_bv[16 * w + g], bv1 = g_bv[16 * w + g + 8];
        const int n = tid & 127, h = tid >> 7;
        const float* xbb = x + (size_t)b * CIN * NN;

        for (int chx = 0; chx < CH; chx++) {
            const int buf = chx & 1;
            if (chx >= 2) BARSYNC(2 + 2 * buf, 512);
            {   // stage x tile (transpose + split)
                const float* xb = xbb + (size_t)(blockIdx.x * CH + chx) * TN + n;
                for (int i = h; i < CIN; i += 2) {
                    bf16 hi, lo;
                    split_bf(xb[(size_t)i * NN], hi, lo);
                    XH[n * XS_ST + i] = hi;
                    XL[n * XS_ST + i] = lo;
                }
            }
            BARSYNC(5, 256);
            bf16* KS = (bf16*)(sm + A_KS0 + buf * ABUF);
            bf16* VS = KS + 17408;   // 34816 bytes
#pragma unroll
            for (int pass = 0; pass < 2; pass++) {
                bf16* OUT = pass ? VS : KS;
                const float bb0 = pass ? bv0 : bk0, bb1 = pass ? bv1 : bk1;
#pragma unroll
                for (int half = 0; half < 2; half++) {
                    float acc[8][4];
#pragma unroll
                    for (int nt = 0; nt < 8; nt++)
#pragma unroll
                        for (int q4 = 0; q4 < 4; q4++) acc[nt][q4] = 0.0f;
#pragma unroll
                    for (int ks = 0; ks < 5; ks++) {
                        uint32_t tH[4], tL[4];
                        const uint32_t *pH, *pL;
                        if (pass) {
                            LDA(tH, WVH, 16 * w, 16 * ks, XS_ST);
                            LDA(tL, WVL, 16 * w, 16 * ks, XS_ST);
                            pH = tH; pL = tL;
                        } else {
                            pH = wkH[ks]; pL = wkL[ks];
                        }
#pragma unroll
                        for (int nt = 0; nt < 8; nt++) {
                            int ntg = half * 8 + nt;
                            uint32_t bH[2], bL[2];
                            LDB(bH, XH, 16 * ks, 8 * ntg, XS_ST);
                            LDB(bL, XL, 16 * ks, 8 * ntg, XS_ST);
                            mma16816(acc[nt], pH, bH);
                            mma16816(acc[nt], pH, bL);
                            mma16816(acc[nt], pL, bH);
                        }
                    }
#pragma unroll
                    for (int nt = 0; nt < 8; nt++) {
                        int ntg = half * 8 + nt;
                        float f0 = fmaxf(acc[nt][0] + bb0, 0.0f);
                        float f1 = fmaxf(acc[nt][1] + bb0, 0.0f);
                        float f2 = fmaxf(acc[nt][2] + bb1, 0.0f);
                        float f3 = fmaxf(acc[nt][3] + bb1, 0.0f);
                        __nv_bfloat162 p01 = __floats2bfloat162_rn(f0, f1);
                        __nv_bfloat162 p23 = __floats2bfloat162_rn(f2, f3);
                        *(uint32_t*)(OUT + (16 * w + g) * BG_ST + 8 * ntg + 2 * tig) = *(uint32_t*)&p01;
                        *(uint32_t*)(OUT + (16 * w + g + 8) * BG_ST + 8 * ntg + 2 * tig) = *(uint32_t*)&p23;
                    }
                }
            }
            BARSYNC(5, 256);          // all proj reads of X done -> safe to restage
            BARARR(1 + 2 * buf, 512); // publish full[buf]
        }
    } else {
        // ---------------- consumer: kv MMA accumulation ----------------------
        const int wc = w - 8;
        float akv[16][4];
#pragma unroll
        for (int nt = 0; nt < 16; nt++)
#pragma unroll
            for (int q4 = 0; q4 < 4; q4++) akv[nt][q4] = 0.0f;

        for (int chx = 0; chx < CH; chx++) {
            const int buf = chx & 1;
            BARSYNC(1 + 2 * buf, 512);
            const bf16* KS = (const bf16*)(sm + A_KS0 + buf * ABUF);
            const bf16* VS = KS + 17408;
#pragma unroll
            for (int ks = 0; ks < 8; ks++) {
                uint32_t aK[4];
                LDA(aK, KS, 16 * wc, 16 * ks, BG_ST);
#pragma unroll
                for (int nt = 0; nt < 16; nt++) {
                    uint32_t bV[2];
                    LDB(bV, VS, 16 * ks, 8 * nt, BG_ST);
                    mma16816(akv[nt], aK, bV);
                }
            }
            BARARR(2 + 2 * buf, 512); // publish empty[buf]
        }
        float* kvb = g_kv + (size_t)b * C2 * C2;
#pragma unroll
        for (int nt = 0; nt < 16; nt++) {
            atomicAdd(&kvb[(16 * wc + g) * C2 + 8 * nt + 2 * tig],     akv[nt][0]);
            atomicAdd(&kvb[(16 * wc + g) * C2 + 8 * nt + 2 * tig + 1], akv[nt][1]);
            atomicAdd(&kvb[(16 * wc + g + 8) * C2 + 8 * nt + 2 * tig],     akv[nt][2]);
            atomicAdd(&kvb[(16 * wc + g + 8) * C2 + 8 * nt + 2 * tig + 1], akv[nt][3]);
        }
    }
}

// ================= K2 =================
__global__ void k2_M(const float* __restrict__ Wf, const float* __restrict__ bnf) {
    int idx = blockIdx.x * blockDim.x + threadIdx.x;
    int b = idx >> 13, r = idx & 8191, o = r >> 7, c = r & 127;
    const float* kvb = g_kv + (size_t)b * C2 * C2 + (size_t)c * C2;
    const float* wf = Wf + o * C2;
    float s = 0.0f;
#pragma unroll 8
    for (int d = 0; d < C2; d++) s = fmaf(wf[d], kvb[d], s);
    float sc = bnf[o] * rsqrtf(bnf[3 * CO + o] + EPSV);
    g_M[idx] = sc * s;
}

// ================= Pass B: warp-specialized q proj -> out GEMM ===============
__global__ void __launch_bounds__(512, 1)
k3_out(const float* __restrict__ x, float* __restrict__ out) {
    extern __shared__ char sm[];
    bf16* XH = (bf16*)(sm + P_XH);
    bf16* XL = (bf16*)(sm + P_XL);
    bf16* MH = (bf16*)(sm + P_MH);
    bf16* ML = (bf16*)(sm + P_ML);
    const int tid = threadIdx.x, w = tid >> 5, lane = tid & 31;
    const int g = lane >> 2, tig = lane & 3;
    const int b = blockIdx.y;

    {   // stage M (split hi/lo); zero X buffers
        const float* Mb = g_M + ((size_t)b << 13);
        for (int j = tid; j < CO * C2; j += 512) {
            int o = j >> 7, c = j & 127;
            bf16 hi, lo;
            split_bf(Mb[j], hi, lo);
            MH[o * BG_ST + c] = hi;
            ML[o * BG_ST + c] = lo;
        }
        for (int j = tid; j < (TN * XS_ST) / 2; j += 512) {
            ((uint32_t*)XH)[j] = 0;
            ((uint32_t*)XL)[j] = 0;
        }
    }
    __syncthreads();

    if (w < 8) {
        // ---------------- producer: stage x + q-proj (Wq in regs) ------------
        uint32_t wqH[5][4], wqL[5][4];
#pragma unroll
        for (int ks = 0; ks < 5; ks++) {
            LDA(wqH[ks], g_WqH, 16 * w, 16 * ks, KP);
            LDA(wqL[ks], g_WqL, 16 * w, 16 * ks, KP);
        }
        const float bq0 = g_bq[16 * w + g], bq1 = g_bq[16 * w + g + 8];
        const int n = tid & 127, h = tid >> 7;
        const float* xbb = x + (size_t)b * CIN * NN;

        for (int chx = 0; chx < CH; chx++) {
            const int buf = chx & 1;
            if (chx >= 2) BARSYNC(2 + 2 * buf, 512);
            {
                const float* xb = xbb + (size_t)(blockIdx.x * CH + chx) * TN + n;
                for (int i = h; i < CIN; i += 2) {
                    bf16 hi, lo;
                    split_bf(xb[(size_t)i * NN], hi, lo);
                    XH[n * XS_ST + i] = hi;
                    XL[n * XS_ST + i] = lo;
                }
            }
            BARSYNC(5, 256);
            bf16* QH = (bf16*)(sm + P_Q0H + buf * PBUF);
            bf16* QL = QH + 17408;
#pragma unroll
            for (int half = 0; half < 2; half++) {
                float acc[8][4];
#pragma unroll
                for (int nt = 0; nt < 8; nt++)
#pragma unroll
                    for (int q4 = 0; q4 < 4; q4++) acc[nt][q4] = 0.0f;
#pragma unroll
                for (int ks = 0; ks < 5; ks++) {
#pragma unroll
                    for (int nt = 0; nt < 8; nt++) {
                        int ntg = half * 8 + nt;
                        uint32_t bH[2], bL[2];
                        LDB(bH, XH, 16 * ks, 8 * ntg, XS_ST);
                        LDB(bL, XL, 16 * ks, 8 * ntg, XS_ST);
                        mma16816(acc[nt], wqH[ks], bH);
                        mma16816(acc[nt], wqH[ks], bL);
                        mma16816(acc[nt], wqL[ks], bH);
                    }
                }
#pragma unroll
                for (int nt = 0; nt < 8; nt++) {
                    int ntg = half * 8 + nt;
                    float f0 = fmaxf(acc[nt][0] + bq0, 0.0f);
                    float f1 = fmaxf(acc[nt][1] + bq0, 0.0f);
                    float f2 = fmaxf(acc[nt][2] + bq1, 0.0f);
                    float f3 = fmaxf(acc[nt][3] + bq1, 0.0f);
                    int na = 8 * ntg + 2 * tig, nb2 = na + 1;
                    bf16 h0, l0, h1, l1, h2, l2, h3, l3;
                    split_bf(f0, h0, l0);
                    split_bf(f1, h1, l1);
                    split_bf(f2, h2, l2);
                    split_bf(f3, h3, l3);
                    QH[na * BG_ST + 16 * w + g] = h0;  QL[na * BG_ST + 16 * w + g] = l0;
                    QH[nb2 * BG_ST + 16 * w + g] = h1; QL[nb2 * BG_ST + 16 * w + g] = l1;
                    QH[na * BG_ST + 16 * w + g + 8] = h2;  QL[na * BG_ST + 16 * w + g + 8] = l2;
                    QH[nb2 * BG_ST + 16 * w + g + 8] = h3; QL[nb2 * BG_ST + 16 * w + g + 8] = l3;
                }
            }
            BARSYNC(5, 256);
            BARARR(1 + 2 * buf, 512);
        }
    } else {
        // ---------------- consumer: out GEMM (M frags hoisted) + STG ---------
        const int wc = w - 8;
        const int o0 = 16 * (wc & 3), nbh = 64 * (wc >> 2);
        uint32_t mHf[8][4], mLf[8][4];
#pragma unroll
        for (int ks = 0; ks < 8; ks++) {
            LDA(mHf[ks], MH, o0, 16 * ks, BG_ST);
            LDA(mLf[ks], ML, o0, 16 * ks, BG_ST);
        }
        const float bo0 = g_bf[o0 + g], bo1 = g_bf[o0 + g + 8];

        for (int chx = 0; chx < CH; chx++) {
            const int buf = chx & 1;
            BARSYNC(1 + 2 * buf, 512);
            const bf16* QH = (const bf16*)(sm + P_Q0H + buf * PBUF);
            const bf16* QL = QH + 17408;
            float acc[8][4];
#pragma unroll
            for (int nt = 0; nt < 8; nt++)
#pragma unroll
                for (int q4 = 0; q4 < 4; q4++) acc[nt][q4] = 0.0f;
#pragma unroll
            for (int ks = 0; ks < 8; ks++) {
#pragma unroll
                for (int nt = 0; nt < 8; nt++) {
                    uint32_t bH[2], bL[2];
                    LDB(bH, QH, 16 * ks, nbh + 8 * nt, BG_ST);
                    LDB(bL, QL, 16 * ks, nbh + 8 * nt, BG_ST);
                    mma16816(acc[nt], mHf[ks], bH);
                    mma16816(acc[nt], mHf[ks], bL);
                    mma16816(acc[nt], mLf[ks], bH);
                }
            }
            const int n0 = (blockIdx.x * CH + chx) * TN;
            float* ob0 = out + ((size_t)(b * CO + o0 + g)) * NN + n0 + nbh;
            float* ob1 = out + ((size_t)(b * CO + o0 + g + 8)) * NN + n0 + nbh;
#pragma unroll
            for (int nt = 0; nt < 8; nt++) {
                float2 v0, v1;
                v0.x = fmaxf(acc[nt][0] + bo0, 0.0f);
                v0.y = fmaxf(acc[nt][1] + bo0, 0.0f);
                v1.x = fmaxf(acc[nt][2] + bo1, 0.0f);
                v1.y = fmaxf(acc[nt][3] + bo1, 0.0f);
                *(float2*)(ob0 + 8 * nt + 2 * tig) = v0;
                *(float2*)(ob1 + 8 * nt + 2 * tig) = v1;
            }
            BARARR(2 + 2 * buf, 512);
        }
    }
}

// ================= launch =================
extern "C" void kernel_launch(void* const* d_in, const int* in_sizes, int n_in,
                              void* d_out, int out_size) {
    const float* x   = (const float*)d_in[0];
    const float* Wq  = (const float*)d_in[1];
    const float* Wk  = (const float*)d_in[2];
    const float* Wv  = (const float*)d_in[3];
    const float* Wf  = (const float*)d_in[4];
    const float* bnq = (const float*)d_in[5];
    const float* bnk = (const float*)d_in[6];
    const float* bnv = (const float*)d_in[7];
    const float* bnf = (const float*)d_in[8];
    float* out = (float*)d_out;

    cudaFuncSetAttribute(k1_kv,  cudaFuncAttributeMaxDynamicSharedMemorySize, A_SZ);
    cudaFuncSetAttribute(k3_out, cudaFuncAttributeMaxDynamicSharedMemorySize, P_SZ);

    const int prep = 3 * C2 * KP + 3 * C2 + CO + B_ * C2 * C2;
    k0_prep<<<(prep + 255) / 256, 256>>>(Wq, Wk, Wv, bnq, bnk, bnv, bnf);
    k1_kv<<<dim3(16, B_), 512, A_SZ>>>(x);
    k2_M<<<(B_ * CO * C2) / 256, 256>>>(Wf, bnf);
    k3_out<<<dim3(16, B_), 512, P_SZ>>>(x, out);
}